// round 13
// baseline (speedup 1.0000x reference)
#include <cuda_runtime.h>

#define BATCH 8
#define LBL 8
#define EDIM 4
#define HT 640
#define WD 640
#define HW (HT*WD)
#define NV4 (HW/4)
#define NV4H (NV4/2)
#define NTHR 256
#define WARPS 8
#define GXA 92                     // kA: 736 blocks = one wave
#define GXD 74                     // kD: 592 blocks = one wave at 4/SM (ILP x2 body)
#define NBLK_D (GXD*BATCH)
#define DIAG 905.0966799187808f

typedef unsigned long long u64;
typedef unsigned int u32;

// ---------- scratch: ALL zero at rest (module load / post-finalize) ----------
__device__ u64   g_occ [BATCH][LBL];      // (max_key<<32)|second_key, key=~idx, 0=empty
__device__ float g_sumk[BATCH][LBL][EDIM];
__device__ float g_cntk[BATCH][LBL];
__device__ float g_cntf[BATCH][LBL];
__device__ float g_lagg[BATCH];
__device__ float g_dr  [BATCH];
__device__ u32   g_c2;
__device__ unsigned char g_lab[BATCH*HW];

// keep the two LARGEST keys at *p
__device__ __forceinline__ void merge_max2(u64* p, u32 k){
  u64 old = *p;
  for(;;){
    u32 g1 = (u32)(old>>32), g2 = (u32)old;
    if (k <= g2) return;
    u32 m1, m2;
    if (k > g1){ m1 = k; m2 = g1; } else { m1 = g1; m2 = k; }
    u64 nv = ((u64)m1<<32) | (u64)m2;
    u64 prev = atomicCAS(p, old, nv);
    if (prev == old) return;
    old = prev;
  }
}

// occurrence update for one subpixel; recompute threshold on the slow path
__device__ __forceinline__ void occ_update(int l, u32 key, u64* s_occ, u32* s_thr){
  if (l > 0){
    u32 lo = ((const u32*)&s_occ[l])[0];   // low word = second-best key
    if (key > lo){
      merge_max2(&s_occ[l], key);
      u32 t = 0xFFFFFFFFu;
      #pragma unroll
      for (int q = 1; q < LBL; q++){
        u32 v = ((const u32*)&s_occ[q])[0];
        t = (v < t) ? v : t;
      }
      *s_thr = t;
    }
  }
}

// ---------------- pass A ----------------
__global__ void __launch_bounds__(NTHR) kA(const float* __restrict__ emb,
                                           const int*   __restrict__ inst,
                                           const float* __restrict__ kern,
                                           const float* __restrict__ tmask){
  const int b    = blockIdx.y;
  const int tid  = threadIdx.x;
  const int w    = tid >> 5;
  const int lane = tid & 31;
  __shared__ float4 s_sum[WARPS][LBL][32];  // 32 KB
  __shared__ u64    s_occ[LBL];
  __shared__ u32    s_thr;
  __shared__ u32    s_cntp[LBL];            // packed (cf | ck<<16)

  for (int i = tid; i < WARPS*LBL*32; i += NTHR)
    ((float4*)s_sum)[i] = make_float4(0.f,0.f,0.f,0.f);
  if (tid < LBL){ s_occ[tid] = 0ull; s_cntp[tid] = 0u; }
  if (tid == 0) s_thr = 0u;
  __syncthreads();

  const float*  eb = emb + (size_t)b*EDIM*HW;
  const int4*   ip = (const int4*)  (inst  + (size_t)b*HW);
  const float4* kp = (const float4*)(kern  + (size_t)b*HW);
  const float4* tp = (const float4*)(tmask + (size_t)b*HW);
  uchar4*       lp = (uchar4*)(g_lab + (size_t)b*HW);

  float4* mysum = &s_sum[w][0][lane];   // + l*32
  u64 cnt_full = 0ull, cnt_kern = 0ull; // 8x8-bit per-label counters

  for (int i = blockIdx.x*NTHR + tid; i < NV4; i += GXA*NTHR){
    int4   iv = __ldcs(ip + i);
    float4 kv = __ldcs(kp + i);
    float4 tv = __ldcs(tp + i);
    float4 e0 = ((const float4*)(eb       ))[i];
    float4 e1 = ((const float4*)(eb +  HW ))[i];
    float4 e2 = ((const float4*)(eb + 2*HW))[i];
    float4 e3 = ((const float4*)(eb + 3*HW))[i];

    int l0 = (tv.x > 0.5f) ? iv.x : 0;
    int l1 = (tv.y > 0.5f) ? iv.y : 0;
    int l2 = (tv.z > 0.5f) ? iv.z : 0;
    int l3 = (tv.w > 0.5f) ? iv.w : 0;
    lp[i] = make_uchar4((unsigned char)l0,(unsigned char)l1,
                        (unsigned char)l2,(unsigned char)l3);
    const int base = i*4;

    if (~(u32)base > s_thr){
      occ_update(l0, ~(u32)(base+0), s_occ, &s_thr);
      occ_update(l1, ~(u32)(base+1), s_occ, &s_thr);
      occ_update(l2, ~(u32)(base+2), s_occ, &s_thr);
      occ_update(l3, ~(u32)(base+3), s_occ, &s_thr);
    }

#define PROC_A(LV, KF, E0, E1, E2, E3)                                       \
    if (LV > 0){                                                             \
      u64 bit = 1ull << (LV*8);                                              \
      cnt_full += bit;                                                       \
      if (KF > 0.5f){                                                        \
        cnt_kern += bit;                                                     \
        float4* p = mysum + LV*32;                                           \
        float4 v = *p;                                                       \
        v.x += E0; v.y += E1; v.z += E2; v.w += E3;                          \
        *p = v;                                                              \
      }                                                                      \
    }
    PROC_A(l0, kv.x, e0.x, e1.x, e2.x, e3.x)
    PROC_A(l1, kv.y, e0.y, e1.y, e2.y, e3.y)
    PROC_A(l2, kv.z, e0.z, e1.z, e2.z, e3.z)
    PROC_A(l3, kv.w, e0.w, e1.w, e2.w, e3.w)
#undef PROC_A
  }

  // byte-wise warp reduction of counters
  cnt_full += __shfl_xor_sync(0xffffffffu, cnt_full, 16);
  cnt_kern += __shfl_xor_sync(0xffffffffu, cnt_kern, 16);
  cnt_full += __shfl_xor_sync(0xffffffffu, cnt_full, 8);
  cnt_kern += __shfl_xor_sync(0xffffffffu, cnt_kern, 8);
  cnt_full += __shfl_xor_sync(0xffffffffu, cnt_full, 4);
  cnt_kern += __shfl_xor_sync(0xffffffffu, cnt_kern, 4);
  if (lane < 4){
    #pragma unroll
    for (int l = 1; l < LBL; l++){
      u32 cf = (u32)(cnt_full >> (l*8)) & 0xffu;
      u32 ck = (u32)(cnt_kern >> (l*8)) & 0xffu;
      u32 pk = cf | (ck << 16);
      if (pk) atomicAdd(&s_cntp[l], pk);
    }
  }
  __syncthreads();

  if (tid < LBL){
    u64 v = s_occ[tid];
    if (v != 0ull){
      merge_max2(&g_occ[b][tid], (u32)(v>>32));
      u32 lo = (u32)v;
      if (lo) merge_max2(&g_occ[b][tid], lo);
    }
    u32 c = s_cntp[tid];
    if (c){
      atomicAdd(&g_cntf[b][tid], (float)(c & 0xFFFFu));
      atomicAdd(&g_cntk[b][tid], (float)(c >> 16));
    }
  }
  {
    int rl = tid >> 5, rt = tid & 31;
    float4 s = make_float4(0.f,0.f,0.f,0.f);
    #pragma unroll
    for (int rw = 0; rw < WARPS; rw++){
      float4 v = s_sum[rw][rl][rt];
      s.x += v.x; s.y += v.y; s.z += v.z; s.w += v.w;
    }
    #pragma unroll
    for (int o = 16; o > 0; o >>= 1){
      s.x += __shfl_down_sync(0xffffffffu, s.x, o);
      s.y += __shfl_down_sync(0xffffffffu, s.y, o);
      s.z += __shfl_down_sync(0xffffffffu, s.z, o);
      s.w += __shfl_down_sync(0xffffffffu, s.w, o);
    }
    if (rt == 0 && rl > 0){
      if (s.x != 0.f) atomicAdd(&g_sumk[b][rl][0], s.x);
      if (s.y != 0.f) atomicAdd(&g_sumk[b][rl][1], s.y);
      if (s.z != 0.f) atomicAdd(&g_sumk[b][rl][2], s.z);
      if (s.w != 0.f) atomicAdd(&g_sumk[b][rl][3], s.w);
    }
  }
}

// ---------------- pass D (+ small math, finalize, reset) ----------------
__global__ void __launch_bounds__(NTHR) kD(const float* __restrict__ emb,
                                           float* __restrict__ out){
  const int b    = blockIdx.y;
  const int tid  = threadIdx.x;
  __shared__ float4 sm4[LBL];
  __shared__ float2 scw[LBL];               // (cd^2, weight)
  __shared__ float  sss[LBL], sst[LBL];
  __shared__ float  red[64];
  __shared__ int    s_last;

  if (tid < LBL){
    float invk = 1.f / fmaxf(g_cntk[b][tid], 1.f);
    float4 m = make_float4(0.f,0.f,0.f,0.f);
    if (tid > 0){
      m.x = g_sumk[b][tid][0]*invk; m.y = g_sumk[b][tid][1]*invk;
      m.z = g_sumk[b][tid][2]*invk; m.w = g_sumk[b][tid][3]*invk;
    }
    sm4[tid] = m;
    u64 v  = g_occ[b][tid];
    u32 f  = ~(u32)(v>>32); if (f  > (u32)(HW-1)) f  = HW-1;
    u32 s2 = ~(u32)v;       if (s2 > (u32)(HW-1)) s2 = HW-1;
    float r0 = (float)(f  / WD), c0 = (float)(f  % WD);
    float r1 = (float)(s2 / WD), c1 = (float)(s2 % WD);
    float dx = r0 - c0, dy = r1 - c1;
    float cd = (tid > 0) ? __expf(__fsqrt_rn(dx*dx + dy*dy) * (0.5f/DIAG)) : 0.f;
    float wt = (tid > 0) ? 1.f / (7.f * fmaxf(g_cntf[b][tid], 1.f)) : 0.f;
    scw[tid] = make_float2(cd*cd, wt);
    sss[tid] = r0 + c0;
    sst[tid] = r1 + c1;
  }
  __syncthreads();

  if (blockIdx.x == 0 && tid < 64){
    int ii = tid>>3, jj = tid&7;
    float acc = 0.f;
    if (ii != jj && ii > 0 && jj > 0){
      float4 a = sm4[ii], c = sm4[jj];
      float dx0=a.x-c.x, dx1=a.y-c.y, dx2=a.z-c.z, dx3=a.w-c.w;
      float Dn = __fsqrt_rn(dx0*dx0+dx1*dx1+dx2*dx2+dx3*dx3);
      float dsp = sss[ii]-sss[jj], dtp = sst[ii]-sst[jj];
      float dp  = __fsqrt_rn(dsp*dsp + dtp*dtp);
      float coef = 1.f - 20.f*__expf(-4.f - 2.5f*dp*(1.f/DIAG));
      float xx = fmaxf(3.f - coef*Dn, 0.f);
      acc = __logf(fmaf(xx,xx,1.f));
    }
    float reg = 0.f;
    if (tid < LBL){
      float4 a = sm4[tid];
      float sq = a.x*a.x + a.y*a.y + a.z*a.z + a.w*a.w;
      reg = __logf(__fsqrt_rn(sq) + 1.f);
    }
    red[tid] = acc*(1.f/42.f) + reg*(0.001f/8.f);
  }
  __syncthreads();
  if (blockIdx.x == 0 && tid < 32){
    float v = red[tid] + red[tid+32];
    #pragma unroll
    for (int o = 16; o > 0; o >>= 1) v += __shfl_down_sync(0xffffffffu, v, o);
    if (tid == 0) g_dr[b] = v;
  }

  const float*  eb = emb + (size_t)b*EDIM*HW;
  const uchar4* lp = (const uchar4*)(g_lab + (size_t)b*HW);
  float acc = 0.f;

  // ILP x2: each iteration loads TWO independent quads (i and i+NV4H)
  // back-to-back before any use -> ~10 loads in flight per thread.
  for (int i = blockIdx.x*NTHR + tid; i < NV4H; i += GXD*NTHR){
    const int j = i + NV4H;
    uchar4 lva = __ldcs(lp + i);
    float4 a0 = __ldcs((const float4*)(eb       ) + i);
    float4 a1 = __ldcs((const float4*)(eb +  HW ) + i);
    float4 a2 = __ldcs((const float4*)(eb + 2*HW) + i);
    float4 a3 = __ldcs((const float4*)(eb + 3*HW) + i);
    uchar4 lvb = __ldcs(lp + j);
    float4 b0 = __ldcs((const float4*)(eb       ) + j);
    float4 b1 = __ldcs((const float4*)(eb +  HW ) + j);
    float4 b2 = __ldcs((const float4*)(eb + 2*HW) + j);
    float4 b3 = __ldcs((const float4*)(eb + 3*HW) + j);

#define PROC_D(LV, E0, E1, E2, E3)                                          \
    {                                                                        \
      float4 m = sm4[LV];                                                    \
      float2 cw = scw[LV];                                                   \
      float d0 = E0 - m.x, d1 = E1 - m.y, d2 = E2 - m.z, d3 = E3 - m.w;      \
      float sq = d0*d0 + d1*d1 + d2*d2 + d3*d3;                              \
      float t  = sq * cw.x;                                                  \
      float dist = t * __frsqrt_rn(fmaxf(t, 1e-30f));                        \
      float xx = fmaxf(dist - 0.5f, 0.f);                                    \
      acc = fmaf(__logf(fmaf(xx,xx,1.f)), cw.y, acc);                        \
    }
    { int l = lva.x; PROC_D(l, a0.x, a1.x, a2.x, a3.x) }
    { int l = lva.y; PROC_D(l, a0.y, a1.y, a2.y, a3.y) }
    { int l = lva.z; PROC_D(l, a0.z, a1.z, a2.z, a3.z) }
    { int l = lva.w; PROC_D(l, a0.w, a1.w, a2.w, a3.w) }
    { int l = lvb.x; PROC_D(l, b0.x, b1.x, b2.x, b3.x) }
    { int l = lvb.y; PROC_D(l, b0.y, b1.y, b2.y, b3.y) }
    { int l = lvb.z; PROC_D(l, b0.z, b1.z, b2.z, b3.z) }
    { int l = lvb.w; PROC_D(l, b0.w, b1.w, b2.w, b3.w) }
#undef PROC_D
  }

  #pragma unroll
  for (int o = 16; o > 0; o >>= 1) acc += __shfl_down_sync(0xffffffffu, acc, o);
  if ((tid & 31) == 0) red[tid>>5] = acc;
  __syncthreads();
  if (tid == 0){
    float t = 0.f;
    #pragma unroll
    for (int k = 0; k < WARPS; k++) t += red[k];
    atomicAdd(&g_lagg[b], t);
  }
  __syncthreads();

  if (tid == 0){
    __threadfence();
    u32 old = atomicAdd(&g_c2, 1u);
    s_last = (old == (u32)(NBLK_D-1));
  }
  __syncthreads();
  if (!s_last) return;
  __threadfence();

  if (tid < BATCH) red[tid] = __ldcg(&g_lagg[tid]) + __ldcg(&g_dr[tid]);
  __syncthreads();
  if (tid == 0){
    float t = 0.f;
    #pragma unroll
    for (int i = 0; i < BATCH; i++) t += red[i];
    out[0] = t*(1.f/BATCH);
    g_c2 = 0u;
  }
  if (tid < BATCH*LBL*EDIM) ((float*)g_sumk)[tid] = 0.f;
  if (tid < BATCH*LBL){
    ((u64*)g_occ)[tid]    = 0ull;
    ((float*)g_cntk)[tid] = 0.f;
    ((float*)g_cntf)[tid] = 0.f;
  }
  if (tid < BATCH) g_lagg[tid] = 0.f;
}

extern "C" void kernel_launch(void* const* d_in, const int* in_sizes, int n_in,
                              void* d_out, int out_size){
  const float* emb   = (const float*)d_in[0];
  const int*   inst  = (const int*)  d_in[1];
  const float* kern  = (const float*)d_in[2];
  const float* tmask = (const float*)d_in[3];
  // d_in[4] = bboxes, unused

  kA<<<dim3(GXA, BATCH), NTHR>>>(emb, inst, kern, tmask);
  kD<<<dim3(GXD, BATCH), NTHR>>>(emb, (float*)d_out);
}

// round 14
// speedup vs baseline: 1.0649x; 1.0649x over previous
#include <cuda_runtime.h>

#define BATCH 8
#define LBL 8
#define EDIM 4
#define HT 640
#define WD 640
#define HW (HT*WD)
#define NV4 (HW/4)
#define NTHR 256
#define WARPS 8
#define GX 74                      // 74*8 = 592 blocks = exactly 4/SM on 148 SMs
#define NBLK (GX*BATCH)
#define STRIDE (GX*NTHR)           // 18944
#define ITERS 6                    // ceil(NV4/STRIDE) = ceil(5.405)
#define DIAG 905.0966799187808f

typedef unsigned long long u64;
typedef unsigned int u32;

// ---------- scratch: ALL zero at rest (module load / post-finalize) ----------
__device__ u64   g_occ [BATCH][LBL];      // (max_key<<32)|second_key, key=~idx, 0=empty
__device__ float g_sumk[BATCH][LBL][EDIM];
__device__ float g_cntk[BATCH][LBL];
__device__ float g_cntf[BATCH][LBL];
__device__ float g_lagg[BATCH];
__device__ float g_dr  [BATCH];
__device__ u32   g_c1, g_c2;

// keep the two LARGEST keys at *p
__device__ __forceinline__ void merge_max2(u64* p, u32 k){
  u64 old = *p;
  for(;;){
    u32 g1 = (u32)(old>>32), g2 = (u32)old;
    if (k <= g2) return;
    u32 m1, m2;
    if (k > g1){ m1 = k; m2 = g1; } else { m1 = g1; m2 = k; }
    u64 nv = ((u64)m1<<32) | (u64)m2;
    u64 prev = atomicCAS(p, old, nv);
    if (prev == old) return;
    old = prev;
  }
}

__device__ __forceinline__ void occ_update(int l, u32 key, u64* s_occ, u32* s_thr){
  if (l > 0){
    u32 lo = ((const u32*)&s_occ[l])[0];   // low word = second-best key
    if (key > lo){
      merge_max2(&s_occ[l], key);
      u32 t = 0xFFFFFFFFu;
      #pragma unroll
      for (int q = 1; q < LBL; q++){
        u32 v = ((const u32*)&s_occ[q])[0];
        t = (v < t) ? v : t;
      }
      *s_thr = t;
    }
  }
}

__global__ void __launch_bounds__(NTHR, 4) kAll(const float* __restrict__ emb,
                                                const int*   __restrict__ inst,
                                                const float* __restrict__ kern,
                                                const float* __restrict__ tmask,
                                                float* __restrict__ out){
  const int b    = blockIdx.y;
  const int x    = blockIdx.x;
  const int tid  = threadIdx.x;
  const int w    = tid >> 5;
  const int lane = tid & 31;

  __shared__ float4 s_sum[WARPS][LBL][32];  // 32 KB (phase A)
  __shared__ u64    s_occ[LBL];
  __shared__ u32    s_thr;
  __shared__ u32    s_cntp[LBL];
  __shared__ float4 sm4[LBL];               // phase D means
  __shared__ float2 scw[LBL];               // (cd^2, weight)
  __shared__ float  sss[LBL], sst[LBL];
  __shared__ float  red[64];
  __shared__ int    s_last;

  for (int i = tid; i < WARPS*LBL*32; i += NTHR)
    ((float4*)s_sum)[i] = make_float4(0.f,0.f,0.f,0.f);
  if (tid < LBL){ s_occ[tid] = 0ull; s_cntp[tid] = 0u; }
  if (tid == 0) s_thr = 0u;
  __syncthreads();

  const float*  eb = emb + (size_t)b*EDIM*HW;
  const int4*   ip = (const int4*)  (inst  + (size_t)b*HW);
  const float4* kp = (const float4*)(kern  + (size_t)b*HW);
  const float4* tp = (const float4*)(tmask + (size_t)b*HW);

  float4* mysum = &s_sum[w][0][lane];   // + l*32
  u64 cnt_full = 0ull, cnt_kern = 0ull; // 8x8-bit per-label counters (max 24)
  u32 labpk[ITERS];                     // labels cached in registers

  // ---------------- phase A ----------------
  #pragma unroll 1
  for (int it = 0; it < ITERS; it++){
    const int i = x*NTHR + tid + it*STRIDE;
    u32 pk = 0;
    if (i < NV4){
      int4   iv = __ldcs(ip + i);
      float4 kv = __ldcs(kp + i);
      float4 tv = __ldcs(tp + i);
      float4 e0 = ((const float4*)(eb       ))[i];
      float4 e1 = ((const float4*)(eb +  HW ))[i];
      float4 e2 = ((const float4*)(eb + 2*HW))[i];
      float4 e3 = ((const float4*)(eb + 3*HW))[i];

      int l0 = (tv.x > 0.5f) ? iv.x : 0;
      int l1 = (tv.y > 0.5f) ? iv.y : 0;
      int l2 = (tv.z > 0.5f) ? iv.z : 0;
      int l3 = (tv.w > 0.5f) ? iv.w : 0;
      pk = (u32)l0 | ((u32)l1<<8) | ((u32)l2<<16) | ((u32)l3<<24);
      const int base = i*4;

      if (~(u32)base > s_thr){
        occ_update(l0, ~(u32)(base+0), s_occ, &s_thr);
        occ_update(l1, ~(u32)(base+1), s_occ, &s_thr);
        occ_update(l2, ~(u32)(base+2), s_occ, &s_thr);
        occ_update(l3, ~(u32)(base+3), s_occ, &s_thr);
      }

#define PROC_A(LV, KF, E0, E1, E2, E3)                                       \
      if (LV > 0){                                                           \
        u64 bit = 1ull << (LV*8);                                            \
        cnt_full += bit;                                                     \
        if (KF > 0.5f){                                                      \
          cnt_kern += bit;                                                   \
          float4* p = mysum + LV*32;                                         \
          float4 v = *p;                                                     \
          v.x += E0; v.y += E1; v.z += E2; v.w += E3;                        \
          *p = v;                                                            \
        }                                                                    \
      }
      PROC_A(l0, kv.x, e0.x, e1.x, e2.x, e3.x)
      PROC_A(l1, kv.y, e0.y, e1.y, e2.y, e3.y)
      PROC_A(l2, kv.z, e0.z, e1.z, e2.z, e3.z)
      PROC_A(l3, kv.w, e0.w, e1.w, e2.w, e3.w)
#undef PROC_A
    }
    labpk[it] = pk;
  }

  // byte-wise warp reduction of counters
  cnt_full += __shfl_xor_sync(0xffffffffu, cnt_full, 16);
  cnt_kern += __shfl_xor_sync(0xffffffffu, cnt_kern, 16);
  cnt_full += __shfl_xor_sync(0xffffffffu, cnt_full, 8);
  cnt_kern += __shfl_xor_sync(0xffffffffu, cnt_kern, 8);
  cnt_full += __shfl_xor_sync(0xffffffffu, cnt_full, 4);
  cnt_kern += __shfl_xor_sync(0xffffffffu, cnt_kern, 4);
  if (lane < 4){
    #pragma unroll
    for (int l = 1; l < LBL; l++){
      u32 cf = (u32)(cnt_full >> (l*8)) & 0xffu;
      u32 ck = (u32)(cnt_kern >> (l*8)) & 0xffu;
      u32 pk = cf | (ck << 16);
      if (pk) atomicAdd(&s_cntp[l], pk);
    }
  }
  __syncthreads();

  if (tid < LBL){
    u64 v = s_occ[tid];
    if (v != 0ull){
      merge_max2(&g_occ[b][tid], (u32)(v>>32));
      u32 lo = (u32)v;
      if (lo) merge_max2(&g_occ[b][tid], lo);
    }
    u32 c = s_cntp[tid];
    if (c){
      atomicAdd(&g_cntf[b][tid], (float)(c & 0xFFFFu));
      atomicAdd(&g_cntk[b][tid], (float)(c >> 16));
    }
  }
  {
    int rl = tid >> 5, rt = tid & 31;
    float4 s = make_float4(0.f,0.f,0.f,0.f);
    #pragma unroll
    for (int rw = 0; rw < WARPS; rw++){
      float4 v = s_sum[rw][rl][rt];
      s.x += v.x; s.y += v.y; s.z += v.z; s.w += v.w;
    }
    #pragma unroll
    for (int o = 16; o > 0; o >>= 1){
      s.x += __shfl_down_sync(0xffffffffu, s.x, o);
      s.y += __shfl_down_sync(0xffffffffu, s.y, o);
      s.z += __shfl_down_sync(0xffffffffu, s.z, o);
      s.w += __shfl_down_sync(0xffffffffu, s.w, o);
    }
    if (rt == 0 && rl > 0){
      if (s.x != 0.f) atomicAdd(&g_sumk[b][rl][0], s.x);
      if (s.y != 0.f) atomicAdd(&g_sumk[b][rl][1], s.y);
      if (s.z != 0.f) atomicAdd(&g_sumk[b][rl][2], s.z);
      if (s.w != 0.f) atomicAdd(&g_sumk[b][rl][3], s.w);
    }
  }
  __syncthreads();

  // ---------------- grid barrier (4/SM residency guaranteed) ----------------
  if (tid == 0){
    __threadfence();
    atomicAdd(&g_c1, 1u);
    while (*(volatile u32*)&g_c1 < (u32)NBLK) __nanosleep(64);
    __threadfence();
  }
  __syncthreads();

  // ---------------- per-image small math ----------------
  if (tid < LBL){
    float invk = 1.f / fmaxf(__ldcg(&g_cntk[b][tid]), 1.f);
    float4 m = make_float4(0.f,0.f,0.f,0.f);
    if (tid > 0){
      m.x = __ldcg(&g_sumk[b][tid][0])*invk; m.y = __ldcg(&g_sumk[b][tid][1])*invk;
      m.z = __ldcg(&g_sumk[b][tid][2])*invk; m.w = __ldcg(&g_sumk[b][tid][3])*invk;
    }
    sm4[tid] = m;
    u64 v  = __ldcg(&g_occ[b][tid]);
    u32 f  = ~(u32)(v>>32); if (f  > (u32)(HW-1)) f  = HW-1;
    u32 s2 = ~(u32)v;       if (s2 > (u32)(HW-1)) s2 = HW-1;
    float r0 = (float)(f  / WD), c0 = (float)(f  % WD);
    float r1 = (float)(s2 / WD), c1 = (float)(s2 % WD);
    float dx = r0 - c0, dy = r1 - c1;
    float cd = (tid > 0) ? __expf(__fsqrt_rn(dx*dx + dy*dy) * (0.5f/DIAG)) : 0.f;
    float wt = (tid > 0) ? 1.f / (7.f * fmaxf(__ldcg(&g_cntf[b][tid]), 1.f)) : 0.f;
    scw[tid] = make_float2(cd*cd, wt);
    sss[tid] = r0 + c0;
    sst[tid] = r1 + c1;
  }
  __syncthreads();

  if (x == 0 && tid < 64){   // l_dis + l_reg, one block per image
    int ii = tid>>3, jj = tid&7;
    float acc = 0.f;
    if (ii != jj && ii > 0 && jj > 0){
      float4 a = sm4[ii], c = sm4[jj];
      float dx0=a.x-c.x, dx1=a.y-c.y, dx2=a.z-c.z, dx3=a.w-c.w;
      float Dn = __fsqrt_rn(dx0*dx0+dx1*dx1+dx2*dx2+dx3*dx3);
      float dsp = sss[ii]-sss[jj], dtp = sst[ii]-sst[jj];
      float dp  = __fsqrt_rn(dsp*dsp + dtp*dtp);
      float coef = 1.f - 20.f*__expf(-4.f - 2.5f*dp*(1.f/DIAG));
      float xx = fmaxf(3.f - coef*Dn, 0.f);
      acc = __logf(fmaf(xx,xx,1.f));
    }
    float reg = 0.f;
    if (tid < LBL){
      float4 a = sm4[tid];
      float sq = a.x*a.x + a.y*a.y + a.z*a.z + a.w*a.w;
      reg = __logf(__fsqrt_rn(sq) + 1.f);
    }
    red[tid] = acc*(1.f/42.f) + reg*(0.001f/8.f);
  }
  __syncthreads();
  if (x == 0 && tid < 32){
    float v = red[tid] + red[tid+32];
    #pragma unroll
    for (int o = 16; o > 0; o >>= 1) v += __shfl_down_sync(0xffffffffu, v, o);
    if (tid == 0) g_dr[b] = v;
  }

  // ---------------- phase D: emb re-read (L2-resident), labels from regs ----
  float acc = 0.f;
  #pragma unroll 1
  for (int it = 0; it < ITERS; it++){
    const int i = x*NTHR + tid + it*STRIDE;
    if (i < NV4){
      u32 pk = labpk[it];
      float4 e0 = __ldcs((const float4*)(eb       ) + i);
      float4 e1 = __ldcs((const float4*)(eb +  HW ) + i);
      float4 e2 = __ldcs((const float4*)(eb + 2*HW) + i);
      float4 e3 = __ldcs((const float4*)(eb + 3*HW) + i);

#define PROC_D(LV, E0, E1, E2, E3)                                          \
      {                                                                      \
        float4 m = sm4[LV];                                                  \
        float2 cw = scw[LV];                                                 \
        float d0 = E0 - m.x, d1 = E1 - m.y, d2 = E2 - m.z, d3 = E3 - m.w;    \
        float sq = d0*d0 + d1*d1 + d2*d2 + d3*d3;                            \
        float t  = sq * cw.x;                                                \
        float dist = t * __frsqrt_rn(fmaxf(t, 1e-30f));                      \
        float xx = fmaxf(dist - 0.5f, 0.f);                                  \
        acc = fmaf(__logf(fmaf(xx,xx,1.f)), cw.y, acc);                      \
      }
      { int l = (int)(pk      & 0xffu); PROC_D(l, e0.x, e1.x, e2.x, e3.x) }
      { int l = (int)((pk>>8 )& 0xffu); PROC_D(l, e0.y, e1.y, e2.y, e3.y) }
      { int l = (int)((pk>>16)& 0xffu); PROC_D(l, e0.z, e1.z, e2.z, e3.z) }
      { int l = (int)((pk>>24)       ); PROC_D(l, e0.w, e1.w, e2.w, e3.w) }
#undef PROC_D
    }
  }

  #pragma unroll
  for (int o = 16; o > 0; o >>= 1) acc += __shfl_down_sync(0xffffffffu, acc, o);
  if (lane == 0) red[w] = acc;
  __syncthreads();
  if (tid == 0){
    float t = 0.f;
    #pragma unroll
    for (int k = 0; k < WARPS; k++) t += red[k];
    atomicAdd(&g_lagg[b], t);
  }
  __syncthreads();

  // ---------------- completion + finalize by last block ----------------
  if (tid == 0){
    __threadfence();
    u32 old = atomicAdd(&g_c2, 1u);
    s_last = (old == (u32)(NBLK-1));
  }
  __syncthreads();
  if (!s_last) return;
  __threadfence();

  if (tid < BATCH) red[tid] = __ldcg(&g_lagg[tid]) + __ldcg(&g_dr[tid]);
  __syncthreads();
  if (tid == 0){
    float t = 0.f;
    #pragma unroll
    for (int i = 0; i < BATCH; i++) t += red[i];
    out[0] = t*(1.f/BATCH);
    g_c1 = 0u; g_c2 = 0u;
  }
  // reset scratch to zero-at-rest for next graph replay
  if (tid < BATCH*LBL*EDIM) ((float*)g_sumk)[tid] = 0.f;
  if (tid < BATCH*LBL){
    ((u64*)g_occ)[tid]    = 0ull;
    ((float*)g_cntk)[tid] = 0.f;
    ((float*)g_cntf)[tid] = 0.f;
  }
  if (tid < BATCH) g_lagg[tid] = 0.f;
}

extern "C" void kernel_launch(void* const* d_in, const int* in_sizes, int n_in,
                              void* d_out, int out_size){
  const float* emb   = (const float*)d_in[0];
  const int*   inst  = (const int*)  d_in[1];
  const float* kern  = (const float*)d_in[2];
  const float* tmask = (const float*)d_in[3];
  // d_in[4] = bboxes, unused

  kAll<<<dim3(GX, BATCH), NTHR>>>(emb, inst, kern, tmask, (float*)d_out);
}